// round 7
// baseline (speedup 1.0000x reference)
#include <cuda_runtime.h>
#include <cstdint>

// Shapes (fixed by problem)
#define Bz 16
#define Nn 1024
#define Cc 768
#define Dd 384

// GEMM tiling
#define BM 128
#define BN 128
#define BK 16
#define TM 8
#define TN 8

// Static device scratch (no allocations allowed)
__device__ __align__(16) float g_tpg[(size_t)Bz * Nn * (3 * Dd)];     // theta|phi|g, ld = 1152
__device__ __align__(16) float g_attn[(size_t)Bz * Nn * Nn];          // scores / softmax
__device__ __align__(16) float g_od[(size_t)Bz * Nn * Dd];            // attn @ g

// ---------------------------------------------------------------------------
// Loaders: tile is BM(=BN)=128 x BK=16. 2048 floats = 512 float4; 256 threads
// load 2 float4 each.
// ---------------------------------------------------------------------------

// Global [rows x K] row-major (K minor) -> S[k][m] (transposed store)
__device__ __forceinline__ void load_trans(float (*S)[BM], const float* __restrict__ g,
                                           int ldg, int tid) {
#pragma unroll
    for (int u = 0; u < 2; u++) {
        int idx = tid + u * 256;
        int m  = idx >> 2;            // 0..127
        int c4 = (idx & 3) * 4;       // 0,4,8,12
        float4 v = *(const float4*)(g + (size_t)m * ldg + c4);
        S[c4 + 0][m] = v.x;
        S[c4 + 1][m] = v.y;
        S[c4 + 2][m] = v.z;
        S[c4 + 3][m] = v.w;
    }
}

// Global [K x cols] row-major (cols minor) -> S[k][j] (direct store)
__device__ __forceinline__ void load_direct(float (*S)[BN], const float* __restrict__ g,
                                            int ldg, int tid) {
#pragma unroll
    for (int u = 0; u < 2; u++) {
        int idx = tid + u * 256;
        int k = idx >> 5;             // 0..15
        int j = (idx & 31) * 4;       // 0..124
        *(float4*)(&S[k][j]) = *(const float4*)(g + (size_t)k * ldg + j);
    }
}

// ---------------------------------------------------------------------------
// Inner product on the tile: each thread does 8x8 FMAs per k, BK=16 steps.
// ---------------------------------------------------------------------------
__device__ __forceinline__ void mma_tile(const float (*As)[BM], const float (*Bs)[BN],
                                         float acc[TM][TN], int ty, int tx) {
#pragma unroll
    for (int k = 0; k < BK; k++) {
        float4 a0 = *(const float4*)(&As[k][ty * TM]);
        float4 a1 = *(const float4*)(&As[k][ty * TM + 4]);
        float4 b0 = *(const float4*)(&Bs[k][tx * TN]);
        float4 b1 = *(const float4*)(&Bs[k][tx * TN + 4]);
        float a[TM] = {a0.x, a0.y, a0.z, a0.w, a1.x, a1.y, a1.z, a1.w};
        float b[TN] = {b0.x, b0.y, b0.z, b0.w, b1.x, b1.y, b1.z, b1.w};
#pragma unroll
        for (int i = 0; i < TM; i++)
#pragma unroll
            for (int j = 0; j < TN; j++)
                acc[i][j] = fmaf(a[i], b[j], acc[i][j]);
    }
}

// ---------------------------------------------------------------------------
// Kernel 1: fused projections.  tpg[M,1152] = x[M,768] @ [Wt|Wp|Wg] + bias
// grid: (16384/128, 1152/128) = (128, 9)
// ---------------------------------------------------------------------------
__global__ __launch_bounds__(256, 2) void k_proj(
    const float* __restrict__ x,
    const float* __restrict__ Wt, const float* __restrict__ bt,
    const float* __restrict__ Wp, const float* __restrict__ bp,
    const float* __restrict__ Wg, const float* __restrict__ bg)
{
    __shared__ __align__(16) float As[BK][BM];
    __shared__ __align__(16) float Bs[BK][BN];
    const int tid = threadIdx.x;
    const int m0 = blockIdx.x * BM;
    const int n0 = blockIdx.y * BN;      // 0..1151, tile fits in one 384-segment
    const int seg = n0 / Dd;
    const int nW  = n0 % Dd;
    const float* W    = (seg == 0) ? Wt : (seg == 1) ? Wp : Wg;
    const float* bias = (seg == 0) ? bt : (seg == 1) ? bp : bg;

    float acc[TM][TN] = {};
    const int ty = tid >> 4, tx = tid & 15;

    for (int k0 = 0; k0 < Cc; k0 += BK) {
        load_trans(As, x + (size_t)m0 * Cc + k0, Cc, tid);
        load_direct(Bs, W + (size_t)k0 * Dd + nW, Dd, tid);
        __syncthreads();
        mma_tile(As, Bs, acc, ty, tx);
        __syncthreads();
    }

    const int r0 = m0 + ty * TM;
    const int c0 = n0 + tx * TN;
#pragma unroll
    for (int i = 0; i < TM; i++) {
        float* dst = g_tpg + (size_t)(r0 + i) * (3 * Dd) + c0;
#pragma unroll
        for (int j = 0; j < TN; j++)
            dst[j] = acc[i][j] + bias[nW + tx * TN + j];
    }
}

// ---------------------------------------------------------------------------
// Kernel 2: scores.  attn[b,i,j] = (theta_b @ phi_b^T)[i,j] * adj[b,i,j]
// grid: (8, 8, 16)
// ---------------------------------------------------------------------------
__global__ __launch_bounds__(256, 2) void k_score(const float* __restrict__ adj)
{
    __shared__ __align__(16) float As[BK][BM];
    __shared__ __align__(16) float Bs[BK][BN];
    const int tid = threadIdx.x;
    const int b  = blockIdx.z;
    const int i0 = blockIdx.x * BM;
    const int j0 = blockIdx.y * BN;

    const float* th = g_tpg + ((size_t)b * Nn + i0) * (3 * Dd);         // theta rows
    const float* ph = g_tpg + ((size_t)b * Nn + j0) * (3 * Dd) + Dd;    // phi rows

    float acc[TM][TN] = {};
    const int ty = tid >> 4, tx = tid & 15;

    for (int k0 = 0; k0 < Dd; k0 += BK) {
        load_trans(As, th + k0, 3 * Dd, tid);
        load_trans((float(*)[BM])Bs, ph + k0, 3 * Dd, tid);
        __syncthreads();
        mma_tile(As, Bs, acc, ty, tx);
        __syncthreads();
    }

    const size_t base = (size_t)b * Nn * Nn;
    const int r0 = i0 + ty * TM;
    const int c0 = j0 + tx * TN;
#pragma unroll
    for (int i = 0; i < TM; i++) {
        const size_t ro = base + (size_t)(r0 + i) * Nn + c0;
#pragma unroll
        for (int j = 0; j < TN; j++)
            g_attn[ro + j] = acc[i][j] * adj[ro + j];
    }
}

// ---------------------------------------------------------------------------
// Kernel 3: row softmax over last dim (1024). One block per row, 256 threads,
// one float4 per thread.
// ---------------------------------------------------------------------------
__global__ __launch_bounds__(256) void k_softmax()
{
    const size_t row = blockIdx.x;
    float4* p = (float4*)(g_attn + row * Nn);
    float4 v = p[threadIdx.x];

    float m = fmaxf(fmaxf(v.x, v.y), fmaxf(v.z, v.w));
#pragma unroll
    for (int o = 16; o; o >>= 1) m = fmaxf(m, __shfl_xor_sync(0xffffffffu, m, o));
    __shared__ float red[8];
    const int warp = threadIdx.x >> 5;
    if ((threadIdx.x & 31) == 0) red[warp] = m;
    __syncthreads();
    float bm = red[0];
#pragma unroll
    for (int i = 1; i < 8; i++) bm = fmaxf(bm, red[i]);
    __syncthreads();

    v.x = __expf(v.x - bm);
    v.y = __expf(v.y - bm);
    v.z = __expf(v.z - bm);
    v.w = __expf(v.w - bm);
    float s = v.x + v.y + v.z + v.w;
#pragma unroll
    for (int o = 16; o; o >>= 1) s += __shfl_xor_sync(0xffffffffu, s, o);
    if ((threadIdx.x & 31) == 0) red[warp] = s;
    __syncthreads();
    float tot = red[0];
#pragma unroll
    for (int i = 1; i < 8; i++) tot += red[i];

    const float inv = 1.0f / tot;
    v.x *= inv; v.y *= inv; v.z *= inv; v.w *= inv;
    p[threadIdx.x] = v;
}

// ---------------------------------------------------------------------------
// Kernel 4: od[b,i,:] = attn[b,i,:] @ g_b   (M=1024, N=384, K=1024 per batch)
// grid: (8, 3, 16)
// ---------------------------------------------------------------------------
__global__ __launch_bounds__(256, 2) void k_av()
{
    __shared__ __align__(16) float As[BK][BM];
    __shared__ __align__(16) float Bs[BK][BN];
    const int tid = threadIdx.x;
    const int b  = blockIdx.z;
    const int i0 = blockIdx.x * BM;
    const int j0 = blockIdx.y * BN;   // 0,128,256

    const float* A  = g_attn + (size_t)b * Nn * Nn + (size_t)i0 * Nn;
    const float* Bg = g_tpg + (size_t)b * Nn * (3 * Dd) + 2 * Dd + j0;  // g rows

    float acc[TM][TN] = {};
    const int ty = tid >> 4, tx = tid & 15;

    for (int k0 = 0; k0 < Nn; k0 += BK) {
        load_trans(As, A + k0, Nn, tid);
        load_direct(Bs, Bg + (size_t)k0 * (3 * Dd), 3 * Dd, tid);
        __syncthreads();
        mma_tile(As, Bs, acc, ty, tx);
        __syncthreads();
    }

    const int r0 = i0 + ty * TM;
    const int c0 = j0 + tx * TN;
#pragma unroll
    for (int i = 0; i < TM; i++) {
        float* dst = g_od + ((size_t)b * Nn + r0 + i) * Dd + c0;
#pragma unroll
        for (int j = 0; j < TN; j++) dst[j] = acc[i][j];
    }
}

// ---------------------------------------------------------------------------
// Kernel 5: out = od @ W_out + b_out + x   (M=16384, N=768, K=384)
// grid: (128, 6)
// ---------------------------------------------------------------------------
__global__ __launch_bounds__(256, 2) void k_out(
    const float* __restrict__ x,
    const float* __restrict__ Wo, const float* __restrict__ bo,
    float* __restrict__ out)
{
    __shared__ __align__(16) float As[BK][BM];
    __shared__ __align__(16) float Bs[BK][BN];
    const int tid = threadIdx.x;
    const int m0 = blockIdx.x * BM;
    const int n0 = blockIdx.y * BN;

    float acc[TM][TN] = {};
    const int ty = tid >> 4, tx = tid & 15;

    for (int k0 = 0; k0 < Dd; k0 += BK) {
        load_trans(As, g_od + (size_t)m0 * Dd + k0, Dd, tid);
        load_direct(Bs, Wo + (size_t)k0 * Cc + n0, Cc, tid);
        __syncthreads();
        mma_tile(As, Bs, acc, ty, tx);
        __syncthreads();
    }

    const int r0 = m0 + ty * TM;
    const int c0 = n0 + tx * TN;
#pragma unroll
    for (int i = 0; i < TM; i++) {
        const size_t ro = (size_t)(r0 + i) * Cc + c0;
#pragma unroll
        for (int j = 0; j < TN; j++)
            out[ro + j] = acc[i][j] + bo[n0 % Cc + tx * TN + j] + x[ro + j];
    }
}

// ---------------------------------------------------------------------------
extern "C" void kernel_launch(void* const* d_in, const int* in_sizes, int n_in,
                              void* d_out, int out_size)
{
    const float* x  = (const float*)d_in[0];
    const float* adj = (const float*)d_in[1];
    const float* Wt = (const float*)d_in[2];
    const float* bt = (const float*)d_in[3];
    const float* Wp = (const float*)d_in[4];
    const float* bp = (const float*)d_in[5];
    const float* Wg = (const float*)d_in[6];
    const float* bg = (const float*)d_in[7];
    const float* Wo = (const float*)d_in[8];
    const float* bo = (const float*)d_in[9];
    float* out = (float*)d_out;

    dim3 blk(256);

    // 1) projections: theta|phi|g
    k_proj<<<dim3((Bz * Nn) / BM, (3 * Dd) / BN), blk>>>(x, Wt, bt, Wp, bp, Wg, bg);

    // 2) masked scores
    k_score<<<dim3(Nn / BM, Nn / BN, Bz), blk>>>(adj);

    // 3) softmax over rows
    k_softmax<<<dim3(Bz * Nn), blk>>>();

    // 4) attn @ g
    k_av<<<dim3(Nn / BM, Dd / BN, Bz), blk>>>();

    // 5) output projection + bias + residual
    k_out<<<dim3((Bz * Nn) / BM, Cc / BN), blk>>>(x, Wo, bo, out);
}

// round 9
// speedup vs baseline: 2.4658x; 2.4658x over previous
#include <cuda_runtime.h>
#include <cuda_bf16.h>
#include <cstdint>

#define Bz 16
#define Nn 1024
#define Cc 768
#define Dd 384

#define KP_PROJ 2304
#define KP_SC   1152
#define KP_AV   3072
#define KP_OUT  1152

#define KC 64                       // bf16 K elems per chunk (=128B rows)
#define TILE_B  16384               // 128 x 128B, one operand tile
#define STAGE_B 32768               // A tile + B tile
#define SMEM_DYN (2*STAGE_B + 128)

// ---------------- static scratch ----------------
__device__ __align__(16) __nv_bfloat16 g_xA3 [(size_t)Bz*Nn*KP_PROJ];
__device__ __align__(16) __nv_bfloat16 g_wB3 [(size_t)3*Dd*KP_PROJ];
__device__              float          g_bias[3*Dd];
__device__ __align__(16) __nv_bfloat16 g_thA3[(size_t)Bz*Nn*KP_SC];
__device__ __align__(16) __nv_bfloat16 g_phB3[(size_t)Bz*Nn*KP_SC];
__device__ __align__(16) __nv_bfloat16 g_gB3 [(size_t)Bz*Dd*KP_AV];
__device__ __align__(16) float         g_attn[(size_t)Bz*Nn*Nn];
__device__ __align__(16) __nv_bfloat16 g_at3 [(size_t)Bz*Nn*KP_AV];
__device__ __align__(16) __nv_bfloat16 g_od3 [(size_t)Bz*Nn*KP_OUT];
__device__ __align__(16) __nv_bfloat16 g_woB3[(size_t)Cc*KP_OUT];

// ---------------- helpers ----------------
__device__ __forceinline__ uint32_t smem_u32(const void* p){
    uint32_t a;
    asm("{ .reg .u64 t; cvta.to.shared.u64 t, %1; cvt.u32.u64 %0, t; }" : "=r"(a) : "l"(p));
    return a;
}
__device__ __forceinline__ void cpa16(uint32_t dst, const void* src){
    asm volatile("cp.async.cg.shared.global [%0], [%1], 16;" :: "r"(dst), "l"(src));
}
#define CP_COMMIT() asm volatile("cp.async.commit_group;" ::: "memory")
#define CP_WAIT(N)  asm volatile("cp.async.wait_group %0;" :: "n"(N) : "memory")

__device__ __forceinline__ void ldsm4(uint32_t (&d)[4], uint32_t a){
    asm volatile("ldmatrix.sync.aligned.m8n8.x4.shared.b16 {%0,%1,%2,%3}, [%4];"
        : "=r"(d[0]), "=r"(d[1]), "=r"(d[2]), "=r"(d[3]) : "r"(a));
}
__device__ __forceinline__ void ldsm2(uint32_t (&d)[2], uint32_t a){
    asm volatile("ldmatrix.sync.aligned.m8n8.x2.shared.b16 {%0,%1}, [%2];"
        : "=r"(d[0]), "=r"(d[1]) : "r"(a));
}
__device__ __forceinline__ void mma16816(float (&c)[4], const uint32_t (&a)[4], const uint32_t (&b)[2]){
    asm volatile("mma.sync.aligned.m16n8k16.row.col.f32.bf16.bf16.f32 "
        "{%0,%1,%2,%3}, {%4,%5,%6,%7}, {%8,%9}, {%0,%1,%2,%3};"
        : "+f"(c[0]), "+f"(c[1]), "+f"(c[2]), "+f"(c[3])
        : "r"(a[0]), "r"(a[1]), "r"(a[2]), "r"(a[3]), "r"(b[0]), "r"(b[1]));
}

__device__ __forceinline__ uint32_t bf2u(__nv_bfloat16 a, __nv_bfloat16 b){
    return (uint32_t)__bfloat16_as_ushort(a) | ((uint32_t)__bfloat16_as_ushort(b) << 16);
}
__device__ __forceinline__ void split_bf(float v, __nv_bfloat16& h, __nv_bfloat16& l){
    h = __float2bfloat16(v);
    l = __float2bfloat16(v - __bfloat162float(h));
}

// ---------------- HMMA GEMM core: 128x128 CTA tile, 8 warps, KC=64 ----------------
// A: [M x ld] row-major bf16 (K minor), B: [N x ld] row-major bf16 (K minor).
// acc[mi][ni][4] per thread; warp (wr=w>>2, wc=w&3) owns rows wr*64+mi*16, cols wc*32+ni*8.
__device__ __forceinline__ void gemm_hmma(
    const __nv_bfloat16* __restrict__ A, int ldA,
    const __nv_bfloat16* __restrict__ B, int ldB,
    int nch, char* sm, float acc[4][4][4])
{
    const int tid  = threadIdx.x;
    const int lane = tid & 31;
    const int w    = tid >> 5;
    const int wr   = w >> 2, wc = w & 3;
    const uint32_t sbase = (smem_u32(sm) + 127u) & ~127u;

    // gmem->smem: 4 x 16B per thread per operand
    int goA[4], goB[4], smo[4];
#pragma unroll
    for (int i = 0; i < 4; i++){
        int idx = i * 256 + tid;
        int rr = idx >> 3, cc = idx & 7;
        goA[i] = rr * ldA + cc * 8;
        goB[i] = rr * ldB + cc * 8;
        smo[i] = rr * 128 + ((cc * 16) ^ ((rr & 7) << 4));
    }

    // ldmatrix address pieces
    const int xorv = (lane & 7) << 4;
    int arow[4], brow[4];
#pragma unroll
    for (int mi = 0; mi < 4; mi++) arow[mi] = (wr * 64 + mi * 16 + (lane & 15)) * 128;
#pragma unroll
    for (int ni = 0; ni < 4; ni++) brow[ni] = (wc * 32 + ni * 8 + (lane & 7)) * 128;
    const int acs = (lane & 16);        // A col select (0/16B)
    const int bcs = (lane & 8) << 1;    // B col select (0/16B)

#pragma unroll
    for (int mi = 0; mi < 4; mi++)
#pragma unroll
        for (int ni = 0; ni < 4; ni++)
#pragma unroll
            for (int q = 0; q < 4; q++) acc[mi][ni][q] = 0.f;

    // prologue: issue chunk 0 -> buf 0
    {
        const uint32_t s = sbase;
#pragma unroll
        for (int i = 0; i < 4; i++) cpa16(s + smo[i], A + goA[i]);
#pragma unroll
        for (int i = 0; i < 4; i++) cpa16(s + TILE_B + smo[i], B + goB[i]);
        CP_COMMIT();
    }

    for (int c2 = 0; c2 < nch; ++c2){
        if (c2 + 1 < nch){
            const uint32_t s = sbase + ((c2 + 1) & 1) * STAGE_B;
            const __nv_bfloat16* Ak = A + (c2 + 1) * KC;
            const __nv_bfloat16* Bk = B + (c2 + 1) * KC;
#pragma unroll
            for (int i = 0; i < 4; i++) cpa16(s + smo[i], Ak + goA[i]);
#pragma unroll
            for (int i = 0; i < 4; i++) cpa16(s + TILE_B + smo[i], Bk + goB[i]);
            CP_COMMIT();
            CP_WAIT(1);
        } else {
            CP_WAIT(0);
        }
        __syncthreads();

        const uint32_t sA = sbase + (c2 & 1) * STAGE_B;
        const uint32_t sB = sA + TILE_B;
#pragma unroll
        for (int ks = 0; ks < 4; ks++){
            uint32_t afr[4][4];
#pragma unroll
            for (int mi = 0; mi < 4; mi++)
                ldsm4(afr[mi], sA + arow[mi] + (((ks << 5) | acs) ^ xorv));
#pragma unroll
            for (int ni = 0; ni < 4; ni++){
                uint32_t bfr[2];
                ldsm2(bfr, sB + brow[ni] + (((ks << 5) | bcs) ^ xorv));
#pragma unroll
                for (int mi = 0; mi < 4; mi++)
                    mma16816(acc[mi][ni], afr[mi], bfr);
            }
        }
        __syncthreads();   // protect buffer (c2&1) before next-next issue overwrites it
    }
}

// epilogue index helpers: per (mi, ni, h): row = wr*64+mi*16+(lane>>2)+h*8,
// col = wc*32+ni*8+(lane&3)*2; values acc[mi][ni][h*2], [h*2+1].

// ---------------- conversion kernels ----------------
__global__ __launch_bounds__(256) void k_cvt_x(const float* __restrict__ x){
    const int idx = blockIdx.x * 256 + threadIdx.x;
    const int m = idx / 192, kq = idx % 192;
    float4 v = *(const float4*)(x + (size_t)m * Cc + kq * 4);
    __nv_bfloat16 h0,h1,h2,h3,l0,l1,l2,l3;
    split_bf(v.x,h0,l0); split_bf(v.y,h1,l1); split_bf(v.z,h2,l2); split_bf(v.w,h3,l3);
    __nv_bfloat16* p = g_xA3 + (size_t)m * KP_PROJ + kq * 4;
    uint2 uh; uh.x = bf2u(h0,h1); uh.y = bf2u(h2,h3);
    uint2 ul; ul.x = bf2u(l0,l1); ul.y = bf2u(l2,l3);
    *(uint2*)(p)        = uh;
    *(uint2*)(p + 768)  = ul;
    *(uint2*)(p + 1536) = uh;
}

__global__ __launch_bounds__(256) void k_cvt_w(
    const float* __restrict__ Wt, const float* __restrict__ bt,
    const float* __restrict__ Wp, const float* __restrict__ bp,
    const float* __restrict__ Wg, const float* __restrict__ bg)
{
    const int idx = blockIdx.x * 256 + threadIdx.x;
    const int n = idx / 192, kq = idx % 192;
    const int which = n / Dd, d = n % Dd;
    const float* W = (which == 0) ? Wt : (which == 1) ? Wp : Wg;
    __nv_bfloat16 h[4], l[4];
#pragma unroll
    for (int t = 0; t < 4; t++)
        split_bf(W[(size_t)(kq * 4 + t) * Dd + d], h[t], l[t]);
    __nv_bfloat16* p = g_wB3 + (size_t)n * KP_PROJ + kq * 4;
    uint2 uh; uh.x = bf2u(h[0],h[1]); uh.y = bf2u(h[2],h[3]);
    uint2 ul; ul.x = bf2u(l[0],l[1]); ul.y = bf2u(l[2],l[3]);
    *(uint2*)(p)        = uh;
    *(uint2*)(p + 768)  = uh;
    *(uint2*)(p + 1536) = ul;
    if (kq == 0){
        const float* bb = (which == 0) ? bt : (which == 1) ? bp : bg;
        g_bias[n] = bb[d];
    }
}

__global__ __launch_bounds__(256) void k_cvt_wo(const float* __restrict__ Wo){
    const int idx = blockIdx.x * 256 + threadIdx.x;
    const int n = idx / 96, kq = idx % 96;
    __nv_bfloat16 h[4], l[4];
#pragma unroll
    for (int t = 0; t < 4; t++)
        split_bf(Wo[(size_t)(kq * 4 + t) * Cc + n], h[t], l[t]);
    __nv_bfloat16* p = g_woB3 + (size_t)n * KP_OUT + kq * 4;
    uint2 uh; uh.x = bf2u(h[0],h[1]); uh.y = bf2u(h[2],h[3]);
    uint2 ul; ul.x = bf2u(l[0],l[1]); ul.y = bf2u(l[2],l[3]);
    *(uint2*)(p)       = uh;
    *(uint2*)(p + 384) = uh;
    *(uint2*)(p + 768) = ul;
}

// ---------------- GEMM 1: projections ----------------
__global__ __launch_bounds__(256) void k_proj_t(){
    extern __shared__ char sm[];
    const int lane = threadIdx.x & 31, w = threadIdx.x >> 5;
    const int wr = w >> 2, wc = w & 3;
    const int n0 = blockIdx.x * 128, m0 = blockIdx.y * 128;
    float acc[4][4][4];
    gemm_hmma(g_xA3 + (size_t)m0 * KP_PROJ, KP_PROJ,
              g_wB3 + (size_t)n0 * KP_PROJ, KP_PROJ, KP_PROJ / KC, sm, acc);

    const int seg = n0 / Dd, d0 = n0 % Dd;
#pragma unroll
    for (int mi = 0; mi < 4; mi++)
#pragma unroll
    for (int ni = 0; ni < 4; ni++)
#pragma unroll
    for (int h = 0; h < 2; h++){
        const int r   = wr * 64 + mi * 16 + (lane >> 2) + h * 8;
        const int col = wc * 32 + ni * 8 + (lane & 3) * 2;
        const int mrow = m0 + r;
        const int ng = n0 + col;
        float v0 = acc[mi][ni][h * 2]     + g_bias[ng];
        float v1 = acc[mi][ni][h * 2 + 1] + g_bias[ng + 1];
        __nv_bfloat16 h0, l0, h1, l1;
        split_bf(v0, h0, l0); split_bf(v1, h1, l1);
        const uint32_t uh = bf2u(h0, h1), ul = bf2u(l0, l1);
        const int d = d0 + col;
        if (seg == 0){
            __nv_bfloat16* p = g_thA3 + (size_t)mrow * KP_SC + d;   // A: [hi|lo|hi]
            *(uint32_t*)(p) = uh; *(uint32_t*)(p + 384) = ul; *(uint32_t*)(p + 768) = uh;
        } else if (seg == 1){
            __nv_bfloat16* p = g_phB3 + (size_t)mrow * KP_SC + d;   // B: [hi|hi|lo]
            *(uint32_t*)(p) = uh; *(uint32_t*)(p + 384) = uh; *(uint32_t*)(p + 768) = ul;
        } else {
            const int b = mrow >> 10, ml = mrow & 1023;             // g transposed -> B layout
            __nv_bfloat16* q0 = g_gB3 + (size_t)(b * Dd + d)     * KP_AV + ml;
            __nv_bfloat16* q1 = g_gB3 + (size_t)(b * Dd + d + 1) * KP_AV + ml;
            q0[0] = h0; q0[1024] = h0; q0[2048] = l0;
            q1[0] = h1; q1[1024] = h1; q1[2048] = l1;
        }
    }
}

// ---------------- GEMM 2: scores = (theta @ phi^T) * adj ----------------
__global__ __launch_bounds__(256) void k_score_t(const float* __restrict__ adj){
    extern __shared__ char sm[];
    const int lane = threadIdx.x & 31, w = threadIdx.x >> 5;
    const int wr = w >> 2, wc = w & 3;
    const int b = blockIdx.z, j0 = blockIdx.x * 128, i0 = blockIdx.y * 128;
    float acc[4][4][4];
    gemm_hmma(g_thA3 + (size_t)(b * Nn + i0) * KP_SC, KP_SC,
              g_phB3 + (size_t)(b * Nn + j0) * KP_SC, KP_SC, KP_SC / KC, sm, acc);

#pragma unroll
    for (int mi = 0; mi < 4; mi++)
#pragma unroll
    for (int ni = 0; ni < 4; ni++)
#pragma unroll
    for (int h = 0; h < 2; h++){
        const int i = i0 + wr * 64 + mi * 16 + (lane >> 2) + h * 8;
        const int j = j0 + wc * 32 + ni * 8 + (lane & 3) * 2;
        const size_t idx = ((size_t)b * Nn + i) * Nn + j;
        const float2 a2 = *(const float2*)(adj + idx);
        float2 o;
        o.x = acc[mi][ni][h * 2]     * a2.x;
        o.y = acc[mi][ni][h * 2 + 1] * a2.y;
        *(float2*)(g_attn + idx) = o;
    }
}

// ---------------- softmax + bf16 split ----------------
__global__ __launch_bounds__(256) void k_softmax2(){
    const size_t row = blockIdx.x;
    const float4 v = ((const float4*)(g_attn + row * Nn))[threadIdx.x];

    float m = fmaxf(fmaxf(v.x, v.y), fmaxf(v.z, v.w));
#pragma unroll
    for (int o = 16; o; o >>= 1) m = fmaxf(m, __shfl_xor_sync(0xffffffffu, m, o));
    __shared__ float red[8];
    const int warp = threadIdx.x >> 5;
    if ((threadIdx.x & 31) == 0) red[warp] = m;
    __syncthreads();
    float bm = red[0];
#pragma unroll
    for (int i = 1; i < 8; i++) bm = fmaxf(bm, red[i]);
    __syncthreads();

    float4 e;
    e.x = __expf(v.x - bm); e.y = __expf(v.y - bm);
    e.z = __expf(v.z - bm); e.w = __expf(v.w - bm);
    float s = e.x + e.y + e.z + e.w;
#pragma unroll
    for (int o = 16; o; o >>= 1) s += __shfl_xor_sync(0xffffffffu, s, o);
    if ((threadIdx.x & 31) == 0) red[warp] = s;
    __syncthreads();
    float tot = red[0];
#pragma unroll
    for (int i = 1; i < 8; i++) tot += red[i];
    const float inv = 1.0f / tot;
    e.x *= inv; e.y *= inv; e.z *= inv; e.w *= inv;

    __nv_bfloat16 h0,h1,h2,h3,l0,l1,l2,l3;
    split_bf(e.x,h0,l0); split_bf(e.y,h1,l1); split_bf(e.z,h2,l2); split_bf(e.w,h3,l3);
    __nv_bfloat16* p = g_at3 + row * KP_AV + threadIdx.x * 4;
    uint2 uh; uh.x = bf2u(h0,h1); uh.y = bf2u(h2,h3);
    uint2 ul; ul.x = bf2u(l0,l1); ul.y = bf2u(l2,l3);
    *(uint2*)(p)        = uh;   // [hi|lo|hi]
    *(uint2*)(p + 1024) = ul;
    *(uint2*)(p + 2048) = uh;
}

// ---------------- GEMM 3: attn @ g ----------------
__global__ __launch_bounds__(256) void k_av_t(){
    extern __shared__ char sm[];
    const int lane = threadIdx.x & 31, w = threadIdx.x >> 5;
    const int wr = w >> 2, wc = w & 3;
    const int b = blockIdx.z, n0 = blockIdx.x * 128, i0 = blockIdx.y * 128;
    float acc[4][4][4];
    gemm_hmma(g_at3 + (size_t)(b * Nn + i0) * KP_AV, KP_AV,
              g_gB3 + (size_t)(b * Dd + n0) * KP_AV, KP_AV, KP_AV / KC, sm, acc);

#pragma unroll
    for (int mi = 0; mi < 4; mi++)
#pragma unroll
    for (int ni = 0; ni < 4; ni++)
#pragma unroll
    for (int h = 0; h < 2; h++){
        const int r   = wr * 64 + mi * 16 + (lane >> 2) + h * 8;
        const int col = wc * 32 + ni * 8 + (lane & 3) * 2;
        const int mrow = b * Nn + i0 + r;
        __nv_bfloat16 h0, l0, h1, l1;
        split_bf(acc[mi][ni][h * 2],     h0, l0);
        split_bf(acc[mi][ni][h * 2 + 1], h1, l1);
        __nv_bfloat16* p = g_od3 + (size_t)mrow * KP_OUT + n0 + col;  // A: [hi|lo|hi]
        *(uint32_t*)(p)       = bf2u(h0, h1);
        *(uint32_t*)(p + 384) = bf2u(l0, l1);
        *(uint32_t*)(p + 768) = bf2u(h0, h1);
    }
}

// ---------------- GEMM 4: output + bias + residual ----------------
__global__ __launch_bounds__(256) void k_out_t(
    const float* __restrict__ x, const float* __restrict__ bo, float* __restrict__ out)
{
    extern __shared__ char sm[];
    const int lane = threadIdx.x & 31, w = threadIdx.x >> 5;
    const int wr = w >> 2, wc = w & 3;
    const int n0 = blockIdx.x * 128, m0 = blockIdx.y * 128;
    float acc[4][4][4];
    gemm_hmma(g_od3 + (size_t)m0 * KP_OUT, KP_OUT,
              g_woB3 + (size_t)n0 * KP_OUT, KP_OUT, KP_OUT / KC, sm, acc);

#pragma unroll
    for (int mi = 0; mi < 4; mi++)
#pragma unroll
    for (int ni = 0; ni < 4; ni++)
#pragma unroll
    for (int h = 0; h < 2; h++){
        const int row = m0 + wr * 64 + mi * 16 + (lane >> 2) + h * 8;
        const int cg  = n0 + wc * 32 + ni * 8 + (lane & 3) * 2;
        const size_t idx = (size_t)row * Cc + cg;
        const float2 xv = *(const float2*)(x + idx);
        const float2 bv = *(const float2*)(bo + cg);
        float2 o;
        o.x = acc[mi][ni][h * 2]     + bv.x + xv.x;
        o.y = acc[mi][ni][h * 2 + 1] + bv.y + xv.y;
        *(float2*)(out + idx) = o;
    }
}

// ---------------------------------------------------------------------------
extern "C" void kernel_launch(void* const* d_in, const int* in_sizes, int n_in,
                              void* d_out, int out_size)
{
    const float* x  = (const float*)d_in[0];
    const float* adj = (const float*)d_in[1];
    const float* Wt = (const float*)d_in[2];
    const float* bt = (const float*)d_in[3];
    const float* Wp = (const float*)d_in[4];
    const float* bp = (const float*)d_in[5];
    const float* Wg = (const float*)d_in[6];
    const float* bg = (const float*)d_in[7];
    const float* Wo = (const float*)d_in[8];
    const float* bo = (const float*)d_in[9];
    float* out = (float*)d_out;

    static bool attr_done = false;
    if (!attr_done){
        cudaFuncSetAttribute(k_proj_t,  cudaFuncAttributeMaxDynamicSharedMemorySize, SMEM_DYN);
        cudaFuncSetAttribute(k_score_t, cudaFuncAttributeMaxDynamicSharedMemorySize, SMEM_DYN);
        cudaFuncSetAttribute(k_av_t,    cudaFuncAttributeMaxDynamicSharedMemorySize, SMEM_DYN);
        cudaFuncSetAttribute(k_out_t,   cudaFuncAttributeMaxDynamicSharedMemorySize, SMEM_DYN);
        attr_done = true;
    }

    k_cvt_x <<<(Bz * Nn * 192) / 256, 256>>>(x);
    k_cvt_w <<<(3 * Dd * 192) / 256, 256>>>(Wt, bt, Wp, bp, Wg, bg);
    k_cvt_wo<<<(Cc * 96) / 256, 256>>>(Wo);

    k_proj_t <<<dim3(9, 128),   256, SMEM_DYN>>>();
    k_score_t<<<dim3(8, 8, Bz), 256, SMEM_DYN>>>(adj);
    k_softmax2<<<Bz * Nn, 256>>>();
    k_av_t   <<<dim3(3, 8, Bz), 256, SMEM_DYN>>>();
    k_out_t  <<<dim3(6, 128),   256, SMEM_DYN>>>(x, bo, out);
}

// round 10
// speedup vs baseline: 2.9634x; 1.2018x over previous
#include <cuda_runtime.h>
#include <cuda_bf16.h>
#include <cstdint>

#define Bz 16
#define Nn 1024
#define Cc 768
#define Dd 384

// All GEMM operands stored as [row][2K] bf16: per 32-k block, 64 elems = [hi32|lo32]
// (128B per block-row -> same SW128 staging/swizzle for every operand).
#define LD_X   1536   // 2*768
#define LD_D   768    // 2*384
#define LD_T   2048   // 2*1024

#define TILE_B  16384            // 128 rows x 128B
#define STAGE_B 32768            // A tile + B tile
#define NSTAGE  3
#define SMEM_DYN (NSTAGE*STAGE_B + 128)

// ---------------- static scratch ----------------
__device__ __align__(16) __nv_bfloat16 g_xA2 [(size_t)Bz*Nn*LD_X];   // x hi|lo
__device__ __align__(16) __nv_bfloat16 g_wB2 [(size_t)3*Dd*LD_X];    // [Wt|Wp|Wg]^T hi|lo
__device__              float          g_bias[3*Dd];
__device__ __align__(16) __nv_bfloat16 g_th2 [(size_t)Bz*Nn*LD_D];   // theta
__device__ __align__(16) __nv_bfloat16 g_ph2 [(size_t)Bz*Nn*LD_D];   // phi
__device__ __align__(16) __nv_bfloat16 g_g2  [(size_t)Bz*Dd*LD_T];   // g transposed
__device__ __align__(16) float         g_attn[(size_t)Bz*Nn*Nn];
__device__ __align__(16) __nv_bfloat16 g_at2 [(size_t)Bz*Nn*LD_T];   // softmax rows
__device__ __align__(16) __nv_bfloat16 g_od2 [(size_t)Bz*Nn*LD_D];   // attn@g
__device__ __align__(16) __nv_bfloat16 g_wo2 [(size_t)Cc*LD_D];      // Wo^T

// ---------------- helpers ----------------
__device__ __forceinline__ uint32_t smem_u32(const void* p){
    uint32_t a;
    asm("{ .reg .u64 t; cvta.to.shared.u64 t, %1; cvt.u32.u64 %0, t; }" : "=r"(a) : "l"(p));
    return a;
}
__device__ __forceinline__ void cpa16(uint32_t dst, const void* src){
    asm volatile("cp.async.cg.shared.global [%0], [%1], 16;" :: "r"(dst), "l"(src));
}
#define CP_COMMIT() asm volatile("cp.async.commit_group;" ::: "memory")
#define CP_WAIT(N)  asm volatile("cp.async.wait_group %0;" :: "n"(N) : "memory")

__device__ __forceinline__ void ldsm4(uint32_t (&d)[4], uint32_t a){
    asm volatile("ldmatrix.sync.aligned.m8n8.x4.shared.b16 {%0,%1,%2,%3}, [%4];"
        : "=r"(d[0]), "=r"(d[1]), "=r"(d[2]), "=r"(d[3]) : "r"(a));
}
__device__ __forceinline__ void ldsm2(uint32_t (&d)[2], uint32_t a){
    asm volatile("ldmatrix.sync.aligned.m8n8.x2.shared.b16 {%0,%1}, [%2];"
        : "=r"(d[0]), "=r"(d[1]) : "r"(a));
}
__device__ __forceinline__ void mma16816(float (&c)[4], const uint32_t (&a)[4], const uint32_t (&b)[2]){
    asm volatile("mma.sync.aligned.m16n8k16.row.col.f32.bf16.bf16.f32 "
        "{%0,%1,%2,%3}, {%4,%5,%6,%7}, {%8,%9}, {%0,%1,%2,%3};"
        : "+f"(c[0]), "+f"(c[1]), "+f"(c[2]), "+f"(c[3])
        : "r"(a[0]), "r"(a[1]), "r"(a[2]), "r"(a[3]), "r"(b[0]), "r"(b[1]));
}

__device__ __forceinline__ uint32_t bf2u(__nv_bfloat16 a, __nv_bfloat16 b){
    return (uint32_t)__bfloat16_as_ushort(a) | ((uint32_t)__bfloat16_as_ushort(b) << 16);
}
__device__ __forceinline__ void split_bf(float v, __nv_bfloat16& h, __nv_bfloat16& l){
    h = __float2bfloat16(v);
    l = __float2bfloat16(v - __bfloat162float(h));
}
// store hi pair + lo pair at interleaved hi|lo layout (d even, d,d+1 in same block)
__device__ __forceinline__ void store_hl(__nv_bfloat16* base, int d, float v0, float v1){
    __nv_bfloat16 h0,l0,h1,l1;
    split_bf(v0,h0,l0); split_bf(v1,h1,l1);
    __nv_bfloat16* p = base + ((d >> 5) << 6) + (d & 31);
    *(uint32_t*)(p)      = bf2u(h0,h1);
    *(uint32_t*)(p + 32) = bf2u(l0,l1);
}

// ---------------- 3-term split HMMA GEMM core ----------------
// C = (Ahi+Alo)(Bhi+Blo) ~= Ahi*Bhi + Ahi*Blo + Alo*Bhi, computed per 32-k block
// from one 32KB stage (Ahi/Alo and Bhi/Blo interleaved in the same 128B rows).
// CTA tile 128x128, 8 warps (2x4), warp tile 64x32.
__device__ __forceinline__ void gemm3(
    const __nv_bfloat16* __restrict__ A, int ldA,
    const __nv_bfloat16* __restrict__ B, int ldB,
    int nkb, char* sm, float acc[4][4][4])
{
    const int tid  = threadIdx.x;
    const int lane = tid & 31;
    const int w    = tid >> 5;
    const int wr   = w >> 2, wc = w & 3;
    const uint32_t sbase = (smem_u32(sm) + 127u) & ~127u;

    // gmem->smem: 4 x 16B per thread per operand (128 rows x 128B each)
    int goA[4], goB[4], smo[4];
#pragma unroll
    for (int i = 0; i < 4; i++){
        int idx = i * 256 + tid;
        int rr = idx >> 3, cc = idx & 7;
        goA[i] = rr * ldA + cc * 8;
        goB[i] = rr * ldB + cc * 8;
        smo[i] = rr * 128 + ((cc * 16) ^ ((rr & 7) << 4));
    }

    const int xorv = (lane & 7) << 4;
    int arow[4], brow[4];
#pragma unroll
    for (int mi = 0; mi < 4; mi++) arow[mi] = (wr * 64 + mi * 16 + (lane & 15)) * 128;
#pragma unroll
    for (int ni = 0; ni < 4; ni++) brow[ni] = (wc * 32 + ni * 8 + (lane & 7)) * 128;
    const int acs = (lane & 16);
    const int bcs = (lane & 8) << 1;

#pragma unroll
    for (int mi = 0; mi < 4; mi++)
#pragma unroll
        for (int ni = 0; ni < 4; ni++)
#pragma unroll
            for (int q = 0; q < 4; q++) acc[mi][ni][q] = 0.f;

    // prologue: issue chunks 0,1
#pragma unroll
    for (int pc = 0; pc < 2; pc++){
        const uint32_t s = sbase + pc * STAGE_B;
        const __nv_bfloat16* Ak = A + pc * 64;
        const __nv_bfloat16* Bk = B + pc * 64;
#pragma unroll
        for (int i = 0; i < 4; i++) cpa16(s + smo[i], Ak + goA[i]);
#pragma unroll
        for (int i = 0; i < 4; i++) cpa16(s + TILE_B + smo[i], Bk + goB[i]);
        CP_COMMIT();
    }

    int stg = 0;
    for (int c = 0; c < nkb; ++c){
        if (c + 1 < nkb) { CP_WAIT(1); } else { CP_WAIT(0); }
        __syncthreads();

        const uint32_t sA = sbase + stg * STAGE_B;
        const uint32_t sB = sA + TILE_B;
#pragma unroll
        for (int ks = 0; ks < 2; ks++){
            const int chA = ((ks << 5) | acs);
            const int chB = ((ks << 5) | bcs);
            uint32_t ahi[4][4], bhi[4][2];
#pragma unroll
            for (int ni = 0; ni < 4; ni++) ldsm2(bhi[ni], sB + brow[ni] + (chB ^ xorv));
#pragma unroll
            for (int mi = 0; mi < 4; mi++) ldsm4(ahi[mi], sA + arow[mi] + (chA ^ xorv));
            // pass 1: hi*hi
#pragma unroll
            for (int ni = 0; ni < 4; ni++)
#pragma unroll
                for (int mi = 0; mi < 4; mi++) mma16816(acc[mi][ni], ahi[mi], bhi[ni]);
            // pass 2: hi*lo
            {
                uint32_t blo[4][2];
#pragma unroll
                for (int ni = 0; ni < 4; ni++) ldsm2(blo[ni], sB + brow[ni] + ((chB | 64) ^ xorv));
#pragma unroll
                for (int ni = 0; ni < 4; ni++)
#pragma unroll
                    for (int mi = 0; mi < 4; mi++) mma16816(acc[mi][ni], ahi[mi], blo[ni]);
            }
            // pass 3: lo*hi (reuse ahi registers)
#pragma unroll
            for (int mi = 0; mi < 4; mi++) ldsm4(ahi[mi], sA + arow[mi] + ((chA | 64) ^ xorv));
#pragma unroll
            for (int ni = 0; ni < 4; ni++)
#pragma unroll
                for (int mi = 0; mi < 4; mi++) mma16816(acc[mi][ni], ahi[mi], bhi[ni]);
        }

        // issue chunk c+2 into the stage consumed at c-1 (safe: barrier above)
        if (c + 2 < nkb){
            const int ns = (stg + 2 >= NSTAGE) ? stg + 2 - NSTAGE : stg + 2;
            const uint32_t s = sbase + ns * STAGE_B;
            const __nv_bfloat16* Ak = A + (c + 2) * 64;
            const __nv_bfloat16* Bk = B + (c + 2) * 64;
#pragma unroll
            for (int i = 0; i < 4; i++) cpa16(s + smo[i], Ak + goA[i]);
#pragma unroll
            for (int i = 0; i < 4; i++) cpa16(s + TILE_B + smo[i], Bk + goB[i]);
            CP_COMMIT();
        }
        stg = (stg + 1 == NSTAGE) ? 0 : stg + 1;
    }
}

// ---------------- conversion kernels ----------------
__global__ __launch_bounds__(256) void k_cvt_x(const float* __restrict__ x){
    const int idx = blockIdx.x * 256 + threadIdx.x;
    const int m = idx / 192, kq = idx % 192;
    const int k = kq * 4;
    float4 v = *(const float4*)(x + (size_t)m * Cc + k);
    __nv_bfloat16 h0,h1,h2,h3,l0,l1,l2,l3;
    split_bf(v.x,h0,l0); split_bf(v.y,h1,l1); split_bf(v.z,h2,l2); split_bf(v.w,h3,l3);
    __nv_bfloat16* p = g_xA2 + (size_t)m * LD_X + ((k >> 5) << 6) + (k & 31);
    uint2 uh; uh.x = bf2u(h0,h1); uh.y = bf2u(h2,h3);
    uint2 ul; ul.x = bf2u(l0,l1); ul.y = bf2u(l2,l3);
    *(uint2*)(p)      = uh;
    *(uint2*)(p + 32) = ul;
}

__global__ __launch_bounds__(256) void k_cvt_w(
    const float* __restrict__ Wt, const float* __restrict__ bt,
    const float* __restrict__ Wp, const float* __restrict__ bp,
    const float* __restrict__ Wg, const float* __restrict__ bg)
{
    const int idx = blockIdx.x * 256 + threadIdx.x;
    const int n = idx / 192, kq = idx % 192;
    const int which = n / Dd, d = n % Dd;
    const int k = kq * 4;
    const float* W = (which == 0) ? Wt : (which == 1) ? Wp : Wg;
    __nv_bfloat16 h[4], l[4];
#pragma unroll
    for (int t = 0; t < 4; t++)
        split_bf(W[(size_t)(k + t) * Dd + d], h[t], l[t]);
    __nv_bfloat16* p = g_wB2 + (size_t)n * LD_X + ((k >> 5) << 6) + (k & 31);
    uint2 uh; uh.x = bf2u(h[0],h[1]); uh.y = bf2u(h[2],h[3]);
    uint2 ul; ul.x = bf2u(l[0],l[1]); ul.y = bf2u(l[2],l[3]);
    *(uint2*)(p)      = uh;
    *(uint2*)(p + 32) = ul;
    if (kq == 0){
        const float* bb = (which == 0) ? bt : (which == 1) ? bp : bg;
        g_bias[n] = bb[d];
    }
}

__global__ __launch_bounds__(256) void k_cvt_wo(const float* __restrict__ Wo){
    const int idx = blockIdx.x * 256 + threadIdx.x;
    const int n = idx / 96, kq = idx % 96;
    const int k = kq * 4;
    __nv_bfloat16 h[4], l[4];
#pragma unroll
    for (int t = 0; t < 4; t++)
        split_bf(Wo[(size_t)(k + t) * Cc + n], h[t], l[t]);
    __nv_bfloat16* p = g_wo2 + (size_t)n * LD_D + ((k >> 5) << 6) + (k & 31);
    uint2 uh; uh.x = bf2u(h[0],h[1]); uh.y = bf2u(h[2],h[3]);
    uint2 ul; ul.x = bf2u(l[0],l[1]); ul.y = bf2u(l[2],l[3]);
    *(uint2*)(p)      = uh;
    *(uint2*)(p + 32) = ul;
}

// ---------------- GEMM 1: projections ----------------
__global__ __launch_bounds__(256, 2) void k_proj_t(){
    extern __shared__ char sm[];
    const int lane = threadIdx.x & 31, w = threadIdx.x >> 5;
    const int wr = w >> 2, wc = w & 3;
    const int n0 = blockIdx.x * 128, m0 = blockIdx.y * 128;
    float acc[4][4][4];
    gemm3(g_xA2 + (size_t)m0 * LD_X, LD_X,
          g_wB2 + (size_t)n0 * LD_X, LD_X, Cc / 32, sm, acc);

    const int seg = n0 / Dd, d0 = n0 % Dd;
#pragma unroll
    for (int mi = 0; mi < 4; mi++)
#pragma unroll
    for (int ni = 0; ni < 4; ni++)
#pragma unroll
    for (int h = 0; h < 2; h++){
        const int r   = wr * 64 + mi * 16 + (lane >> 2) + h * 8;
        const int col = wc * 32 + ni * 8 + (lane & 3) * 2;
        const int mrow = m0 + r;
        const int ng = n0 + col;
        const float v0 = acc[mi][ni][h * 2]     + g_bias[ng];
        const float v1 = acc[mi][ni][h * 2 + 1] + g_bias[ng + 1];
        const int d = d0 + col;
        if (seg == 0){
            store_hl(g_th2 + (size_t)mrow * LD_D, d, v0, v1);
        } else if (seg == 1){
            store_hl(g_ph2 + (size_t)mrow * LD_D, d, v0, v1);
        } else {
            const int b = mrow >> 10, ml = mrow & 1023;
            const int off = ((ml >> 5) << 6) + (ml & 31);
            __nv_bfloat16 h0, l0, h1, l1;
            split_bf(v0, h0, l0); split_bf(v1, h1, l1);
            __nv_bfloat16* q0 = g_g2 + (size_t)(b * Dd + d)     * LD_T + off;
            __nv_bfloat16* q1 = g_g2 + (size_t)(b * Dd + d + 1) * LD_T + off;
            q0[0] = h0; q0[32] = l0;
            q1[0] = h1; q1[32] = l1;
        }
    }
}

// ---------------- GEMM 2: scores = (theta @ phi^T) * adj ----------------
__global__ __launch_bounds__(256, 2) void k_score_t(const float* __restrict__ adj){
    extern __shared__ char sm[];
    const int lane = threadIdx.x & 31, w = threadIdx.x >> 5;
    const int wr = w >> 2, wc = w & 3;
    const int b = blockIdx.z, j0 = blockIdx.x * 128, i0 = blockIdx.y * 128;
    float acc[4][4][4];
    gemm3(g_th2 + (size_t)(b * Nn + i0) * LD_D, LD_D,
          g_ph2 + (size_t)(b * Nn + j0) * LD_D, LD_D, Dd / 32, sm, acc);

#pragma unroll
    for (int mi = 0; mi < 4; mi++)
#pragma unroll
    for (int ni = 0; ni < 4; ni++)
#pragma unroll
    for (int h = 0; h < 2; h++){
        const int i = i0 + wr * 64 + mi * 16 + (lane >> 2) + h * 8;
        const int j = j0 + wc * 32 + ni * 8 + (lane & 3) * 2;
        const size_t idx = ((size_t)b * Nn + i) * Nn + j;
        const float2 a2 = *(const float2*)(adj + idx);
        float2 o;
        o.x = acc[mi][ni][h * 2]     * a2.x;
        o.y = acc[mi][ni][h * 2 + 1] * a2.y;
        *(float2*)(g_attn + idx) = o;
    }
}

// ---------------- softmax + hi|lo split ----------------
__global__ __launch_bounds__(256) void k_softmax2(){
    const size_t row = blockIdx.x;
    const float4 v = ((const float4*)(g_attn + row * Nn))[threadIdx.x];

    float m = fmaxf(fmaxf(v.x, v.y), fmaxf(v.z, v.w));
#pragma unroll
    for (int o = 16; o; o >>= 1) m = fmaxf(m, __shfl_xor_sync(0xffffffffu, m, o));
    __shared__ float red[8];
    const int warp = threadIdx.x >> 5;
    if ((threadIdx.x & 31) == 0) red[warp] = m;
    __syncthreads();
    float bm = red[0];
#pragma unroll
    for (int i = 1; i < 8; i++) bm = fmaxf(bm, red[i]);
    __syncthreads();

    float4 e;
    e.x = __expf(v.x - bm); e.y = __expf(v.y - bm);
    e.z = __expf(v.z - bm); e.w = __expf(v.w - bm);
    float s = e.x + e.y + e.z + e.w;
#pragma unroll
    for (int o = 16; o; o >>= 1) s += __shfl_xor_sync(0xffffffffu, s, o);
    if ((threadIdx.x & 31) == 0) red[warp] = s;
    __syncthreads();
    float tot = red[0];
#pragma unroll
    for (int i = 1; i < 8; i++) tot += red[i];
    const float inv = 1.0f / tot;
    e.x *= inv; e.y *= inv; e.z *= inv; e.w *= inv;

    const int t = threadIdx.x * 4;
    __nv_bfloat16 h0,h1,h2,h3,l0,l1,l2,l3;
    split_bf(e.x,h0,l0); split_bf(e.y,h1,l1); split_bf(e.z,h2,l2); split_bf(e.w,h3,l3);
    __nv_bfloat16* p = g_at2 + row * LD_T + ((t >> 5) << 6) + (t & 31);
    uint2 uh; uh.x = bf2u(h0,h1); uh.y = bf2u(h2,h3);
    uint2 ul; ul.x = bf2u(l0,l1); ul.y = bf2u(l2,l3);
    *(uint2*)(p)      = uh;
    *(uint2*)(p + 32) = ul;
}

// ---------------- GEMM 3: attn @ g ----------------
__global__ __launch_bounds__(256, 2) void k_av_t(){
    extern __shared__ char sm[];
    const int lane = threadIdx.x & 31, w = threadIdx.x >> 5;
    const int wr = w >> 2, wc = w & 3;
    const int b = blockIdx.z, n0 = blockIdx.x * 128, i0 = blockIdx.y * 128;
    float acc[4][4][4];
    gemm3(g_at2 + (size_t)(b * Nn + i0) * LD_T, LD_T,
          g_g2  + (size_t)(b * Dd + n0) * LD_T, LD_T, Nn / 32, sm, acc);

#pragma unroll
    for (int mi = 0; mi < 4; mi++)
#pragma unroll
    for (int ni = 0; ni < 4; ni++)
#pragma unroll
    for (int h = 0; h < 2; h++){
        const int r   = wr * 64 + mi * 16 + (lane >> 2) + h * 8;
        const int col = wc * 32 + ni * 8 + (lane & 3) * 2;
        const int mrow = b * Nn + i0 + r;
        store_hl(g_od2 + (size_t)mrow * LD_D, n0 + col,
                 acc[mi][ni][h * 2], acc[mi][ni][h * 2 + 1]);
    }
}

// ---------------- GEMM 4: output + bias + residual ----------------
__global__ __launch_bounds__(256, 2) void k_out_t(
    const float* __restrict__ x, const float* __restrict__ bo, float* __restrict__ out)
{
    extern __shared__ char sm[];
    const int lane = threadIdx.x & 31, w = threadIdx.x >> 5;
    const int wr = w >> 2, wc = w & 3;
    const int n0 = blockIdx.x * 128, m0 = blockIdx.y * 128;
    float acc[4][4][4];
    gemm3(g_od2 + (size_t)m0 * LD_D, LD_D,
          g_wo2 + (size_t)n0 * LD_D, LD_D, Dd / 32, sm, acc);

#pragma unroll
    for (int mi = 0; mi < 4; mi++)
#pragma unroll
    for (int ni = 0; ni < 4; ni++)
#pragma unroll
    for (int h = 0; h < 2; h++){
        const int row = m0 + wr * 64 + mi * 16 + (lane >> 2) + h * 8;
        const int cg  = n0 + wc * 32 + ni * 8 + (lane & 3) * 2;
        const size_t idx = (size_t)row * Cc + cg;
        const float2 xv = *(const float2*)(x + idx);
        const float2 bv = *(const float2*)(bo + cg);
        float2 o;
        o.x = acc[mi][ni][h * 2]     + bv.x + xv.x;
        o.y = acc[mi][ni][h * 2 + 1] + bv.y + xv.y;
        *(float2*)(out + idx) = o;
    }
}

// ---------------------------------------------------------------------------
extern "C" void kernel_launch(void* const* d_in, const int* in_sizes, int n_in,
                              void* d_out, int out_size)
{
    const float* x  = (const float*)d_in[0];
    const float* adj = (const float*)d_in[1];
    const float* Wt = (const float*)d_in[2];
    const float* bt = (const float*)d_in[3];
    const float* Wp = (const float*)d_in[4];
    const float* bp = (const float*)d_in[5];
    const float* Wg = (const float*)d_in[6];
    const float* bg = (const float*)d_in[7];
    const float* Wo = (const float*)d_in[8];
    const float* bo = (const float*)d_in[9];
    float* out = (float*)d_out;

    static bool attr_done = false;
    if (!attr_done){
        cudaFuncSetAttribute(k_proj_t,  cudaFuncAttributeMaxDynamicSharedMemorySize, SMEM_DYN);
        cudaFuncSetAttribute(k_score_t, cudaFuncAttributeMaxDynamicSharedMemorySize, SMEM_DYN);
        cudaFuncSetAttribute(k_av_t,    cudaFuncAttributeMaxDynamicSharedMemorySize, SMEM_DYN);
        cudaFuncSetAttribute(k_out_t,   cudaFuncAttributeMaxDynamicSharedMemorySize, SMEM_DYN);
        attr_done = true;
    }

    k_cvt_x <<<(Bz * Nn * 192) / 256, 256>>>(x);
    k_cvt_w <<<(3 * Dd * 192) / 256, 256>>>(Wt, bt, Wp, bp, Wg, bg);
    k_cvt_wo<<<(Cc * 96) / 256, 256>>>(Wo);

    k_proj_t <<<dim3(9, 128),   256, SMEM_DYN>>>();
    k_score_t<<<dim3(8, 8, Bz), 256, SMEM_DYN>>>(adj);
    k_softmax2<<<Bz * Nn, 256>>>();
    k_av_t   <<<dim3(3, 8, Bz), 256, SMEM_DYN>>>();
    k_out_t  <<<dim3(6, 128),   256, SMEM_DYN>>>(x, bo, out);
}